// round 2
// baseline (speedup 1.0000x reference)
#include <cuda_runtime.h>
#include <math.h>

#define H_DIM 2048
#define NH 16
#define DN 128
#define DR 64
#define DQ 192
#define DV 128
#define KVR 512
#define QR 1536
#define SEQ 2048
#define THETA 100000.0f
#define RMS_EPS 1e-5f

// ---------------- scratch (device globals; no allocation allowed) ----------------
__device__ float g_qlat[SEQ * QR];          // 12.6 MB
__device__ float g_q[SEQ * NH * DQ];        // 25 MB
__device__ float g_kvlat[SEQ * KVR];        // 4 MB
__device__ float g_k[SEQ * NH * DQ];        // 25 MB
__device__ float g_v[SEQ * NH * DV];        // 16 MB
__device__ float g_attn[SEQ * NH * DV];     // 16 MB

// ---------------- SGEMM: C[M,N] = A[M,K] @ B[K,N], all row-major ----------------
// BM=BN=128, BK=16, 256 threads, 8x8 per-thread tile.
// Requires: M%128==0, N%128==0, K%16==0 (true for all shapes here).
__global__ __launch_bounds__(256) void sgemm128(
    const float* __restrict__ A, const float* __restrict__ B,
    float* __restrict__ C, int M, int N, int K)
{
    __shared__ float As[16][128];
    __shared__ float Bs[16][128];

    const int bx = blockIdx.x, by = blockIdx.y;
    const int tid = threadIdx.x;
    const int tx = tid & 15;       // 0..15 -> col group
    const int ty = tid >> 4;       // 0..15 -> row group

    const float* Ab = A + (size_t)by * 128 * K;
    const float* Bb = B + (size_t)bx * 128;

    float acc[8][8];
#pragma unroll
    for (int i = 0; i < 8; i++)
#pragma unroll
        for (int j = 0; j < 8; j++) acc[i][j] = 0.f;

    for (int k0 = 0; k0 < K; k0 += 16) {
        // A tile: 128 rows x 16 cols = 512 float4 -> 2 per thread, store transposed
#pragma unroll
        for (int l = 0; l < 2; l++) {
            int f = tid + l * 256;
            int row = f >> 2;
            int c4 = f & 3;
            float4 av = *reinterpret_cast<const float4*>(Ab + (size_t)row * K + k0 + c4 * 4);
            As[c4 * 4 + 0][row] = av.x;
            As[c4 * 4 + 1][row] = av.y;
            As[c4 * 4 + 2][row] = av.z;
            As[c4 * 4 + 3][row] = av.w;
        }
        // B tile: 16 rows x 128 cols = 512 float4 -> 2 per thread
#pragma unroll
        for (int l = 0; l < 2; l++) {
            int f = tid + l * 256;
            int row = f >> 5;       // /32 float4 per row
            int c4 = f & 31;
            float4 bv = *reinterpret_cast<const float4*>(Bb + (size_t)(k0 + row) * N + c4 * 4);
            *reinterpret_cast<float4*>(&Bs[row][c4 * 4]) = bv;
        }
        __syncthreads();

#pragma unroll
        for (int kk = 0; kk < 16; kk++) {
            float ar[8], br[8];
#pragma unroll
            for (int i = 0; i < 8; i++) ar[i] = As[kk][ty * 8 + i];
#pragma unroll
            for (int j = 0; j < 8; j++) br[j] = Bs[kk][tx * 8 + j];
#pragma unroll
            for (int i = 0; i < 8; i++)
#pragma unroll
                for (int j = 0; j < 8; j++) acc[i][j] = fmaf(ar[i], br[j], acc[i][j]);
        }
        __syncthreads();
    }

    float* Cb = C + (size_t)(by * 128) * N + bx * 128;
#pragma unroll
    for (int i = 0; i < 8; i++) {
#pragma unroll
        for (int j4 = 0; j4 < 2; j4++) {
            float4 cv = make_float4(acc[i][j4 * 4 + 0], acc[i][j4 * 4 + 1],
                                    acc[i][j4 * 4 + 2], acc[i][j4 * 4 + 3]);
            *reinterpret_cast<float4*>(Cb + (size_t)(ty * 8 + i) * N + tx * 8 + j4 * 4) = cv;
        }
    }
}

// ---------------- RMSNorm (in place, one block per row) ----------------
__global__ __launch_bounds__(256) void rmsnorm_kernel(float* x, const float* __restrict__ w, int D)
{
    __shared__ float red[8];
    const int row = blockIdx.x;
    float* xr = x + (size_t)row * D;

    float ss = 0.f;
    for (int i = threadIdx.x; i < D; i += 256) {
        float v = xr[i];
        ss += v * v;
    }
#pragma unroll
    for (int o = 16; o > 0; o >>= 1) ss += __shfl_xor_sync(0xffffffffu, ss, o);
    int wid = threadIdx.x >> 5, lid = threadIdx.x & 31;
    if (lid == 0) red[wid] = ss;
    __syncthreads();
    if (wid == 0) {
        ss = (lid < 8) ? red[lid] : 0.f;
#pragma unroll
        for (int o = 4; o > 0; o >>= 1) ss += __shfl_xor_sync(0xffffffffu, ss, o);
        if (lid == 0) red[0] = ss;
    }
    __syncthreads();
    float inv = rsqrtf(red[0] / (float)D + RMS_EPS);
    for (int i = threadIdx.x; i < D; i += 256) xr[i] = w[i] * xr[i] * inv;
}

// ---------------- RoPE on last DR=64 dims of each head of q and k ----------------
// For j in [0,32): ang = s * theta^(-j/32); (x1,x2)=(pe[j],pe[j+32])
// pe[j] = x1*cos - x2*sin ; pe[j+32] = x2*cos + x1*sin
__global__ __launch_bounds__(256) void rope_kernel(float* q, float* k)
{
    int idx = blockIdx.x * blockDim.x + threadIdx.x;   // SEQ*NH*32
    if (idx >= SEQ * NH * 32) return;
    int j = idx & 31;
    int h = (idx >> 5) & (NH - 1);
    int s = idx >> 9;

    float invf = powf(THETA, -(float)j / 32.0f);
    float ang = (float)s * invf;
    float sn, cs;
    sincosf(ang, &sn, &cs);

    float* qp = q + ((size_t)s * NH + h) * DQ + DN;
    float x1 = qp[j], x2 = qp[j + 32];
    qp[j] = x1 * cs - x2 * sn;
    qp[j + 32] = x2 * cs + x1 * sn;

    float* kp = k + ((size_t)s * NH + h) * DQ + DN;
    x1 = kp[j]; x2 = kp[j + 32];
    kp[j] = x1 * cs - x2 * sn;
    kp[j + 32] = x2 * cs + x1 * sn;
}

// ---------------- Flash attention, fp32, causal ----------------
// grid (SEQ/BQ, NH), 256 threads. Thread t: row r = t>>2 within tile, c = t&3.
// Each row handled by 4 threads: dot over 48-dim slices reduced via shfl;
// each thread accumulates 32 of the 128 V dims.
#define BQ 64
#define BK 32
__global__ __launch_bounds__(256) void attn_kernel(
    const float* __restrict__ q, const float* __restrict__ k,
    const float* __restrict__ v, float* __restrict__ o)
{
    __shared__ float Ks[BK][DQ];   // 24 KB
    __shared__ float Vs[BK][DV];   // 16 KB

    const int qb = blockIdx.x, h = blockIdx.y;
    const int tid = threadIdx.x;
    const int r = tid >> 2;
    const int c = tid & 3;
    const int qrow = qb * BQ + r;
    const float scale = rsqrtf((float)DQ);

    float qf[48];
    const float* qp = q + ((size_t)qrow * NH + h) * DQ + c * 48;
#pragma unroll
    for (int i = 0; i < 12; i++) {
        float4 t = *reinterpret_cast<const float4*>(qp + i * 4);
        qf[i * 4 + 0] = t.x; qf[i * 4 + 1] = t.y; qf[i * 4 + 2] = t.z; qf[i * 4 + 3] = t.w;
    }

    float m = -1e30f, l = 0.f;
    float acc[32];
#pragma unroll
    for (int j = 0; j < 32; j++) acc[j] = 0.f;

    const int ntiles = (qb * BQ + BQ) / BK;   // causal: only tiles with k <= last q row
    for (int t = 0; t < ntiles; t++) {
        const int k0 = t * BK;
        // load K tile: 32 rows * 48 float4 = 1536 float4 -> 6 per thread
#pragma unroll
        for (int li = 0; li < 6; li++) {
            int f = tid + li * 256;
            int row = f / 48;
            int col = f % 48;
            float4 t4 = *reinterpret_cast<const float4*>(
                k + ((size_t)(k0 + row) * NH + h) * DQ + col * 4);
            *reinterpret_cast<float4*>(&Ks[row][col * 4]) = t4;
        }
        // load V tile: 32 rows * 32 float4 = 1024 float4 -> 4 per thread
#pragma unroll
        for (int li = 0; li < 4; li++) {
            int f = tid + li * 256;
            int row = f >> 5;
            int col = f & 31;
            float4 t4 = *reinterpret_cast<const float4*>(
                v + ((size_t)(k0 + row) * NH + h) * DV + col * 4);
            *reinterpret_cast<float4*>(&Vs[row][col * 4]) = t4;
        }
        __syncthreads();

        float sc[BK];
#pragma unroll
        for (int kk = 0; kk < BK; kk++) {
            float p = 0.f;
            const float4* kr4 = reinterpret_cast<const float4*>(&Ks[kk][c * 48]);
#pragma unroll
            for (int d4 = 0; d4 < 12; d4++) {
                float4 t4 = kr4[d4];
                p = fmaf(qf[d4 * 4 + 0], t4.x, p);
                p = fmaf(qf[d4 * 4 + 1], t4.y, p);
                p = fmaf(qf[d4 * 4 + 2], t4.z, p);
                p = fmaf(qf[d4 * 4 + 3], t4.w, p);
            }
            p += __shfl_xor_sync(0xffffffffu, p, 1);
            p += __shfl_xor_sync(0xffffffffu, p, 2);
            p *= scale;
            if (k0 + kk > qrow) p = -1e30f;
            sc[kk] = p;
        }

        float mt = m;
#pragma unroll
        for (int kk = 0; kk < BK; kk++) mt = fmaxf(mt, sc[kk]);
        float corr = __expf(m - mt);
        m = mt;
        l *= corr;
#pragma unroll
        for (int j = 0; j < 32; j++) acc[j] *= corr;

#pragma unroll
        for (int kk = 0; kk < BK; kk++) {
            float p = __expf(sc[kk] - m);
            l += p;
            const float4* vr4 = reinterpret_cast<const float4*>(&Vs[kk][c * 32]);
#pragma unroll
            for (int j4 = 0; j4 < 8; j4++) {
                float4 t4 = vr4[j4];
                acc[j4 * 4 + 0] = fmaf(p, t4.x, acc[j4 * 4 + 0]);
                acc[j4 * 4 + 1] = fmaf(p, t4.y, acc[j4 * 4 + 1]);
                acc[j4 * 4 + 2] = fmaf(p, t4.z, acc[j4 * 4 + 2]);
                acc[j4 * 4 + 3] = fmaf(p, t4.w, acc[j4 * 4 + 3]);
            }
        }
        __syncthreads();
    }

    float invl = 1.0f / l;
    float* op = o + ((size_t)qrow * NH + h) * DV + c * 32;
#pragma unroll
    for (int j4 = 0; j4 < 8; j4++) {
        float4 t4 = make_float4(acc[j4 * 4 + 0] * invl, acc[j4 * 4 + 1] * invl,
                                acc[j4 * 4 + 2] * invl, acc[j4 * 4 + 3] * invl);
        *reinterpret_cast<float4*>(op + j4 * 4) = t4;
    }
}

// ---------------- host launcher ----------------
extern "C" void kernel_launch(void* const* d_in, const int* in_sizes, int n_in,
                              void* d_out, int out_size)
{
    const float* x        = (const float*)d_in[0];   // [S, H]
    const float* wq_down  = (const float*)d_in[1];   // [H, QR]
    const float* q_norm_w = (const float*)d_in[2];   // [QR]
    const float* wq_up    = (const float*)d_in[3];   // [QR, NH*DQ]
    const float* wkv_down = (const float*)d_in[4];   // [H, KVR]
    const float* kv_norm_w= (const float*)d_in[5];   // [KVR]
    const float* wk_up    = (const float*)d_in[6];   // [KVR, NH*DQ]
    const float* wv_up    = (const float*)d_in[7];   // [KVR, NH*DV]
    const float* wo       = (const float*)d_in[8];   // [NH*DV, H]
    float* out = (float*)d_out;

    float *qlat, *qbuf, *kvlat, *kbuf, *vbuf, *attn;
    cudaGetSymbolAddress((void**)&qlat,  g_qlat);
    cudaGetSymbolAddress((void**)&qbuf,  g_q);
    cudaGetSymbolAddress((void**)&kvlat, g_kvlat);
    cudaGetSymbolAddress((void**)&kbuf,  g_k);
    cudaGetSymbolAddress((void**)&vbuf,  g_v);
    cudaGetSymbolAddress((void**)&attn,  g_attn);

    dim3 thr(256);

    // q path
    sgemm128<<<dim3(QR / 128, SEQ / 128), thr>>>(x, wq_down, qlat, SEQ, QR, H_DIM);
    rmsnorm_kernel<<<SEQ, thr>>>(qlat, q_norm_w, QR);
    sgemm128<<<dim3((NH * DQ) / 128, SEQ / 128), thr>>>(qlat, wq_up, qbuf, SEQ, NH * DQ, QR);

    // kv path
    sgemm128<<<dim3(KVR / 128, SEQ / 128), thr>>>(x, wkv_down, kvlat, SEQ, KVR, H_DIM);
    rmsnorm_kernel<<<SEQ, thr>>>(kvlat, kv_norm_w, KVR);
    sgemm128<<<dim3((NH * DQ) / 128, SEQ / 128), thr>>>(kvlat, wk_up, kbuf, SEQ, NH * DQ, KVR);
    sgemm128<<<dim3((NH * DV) / 128, SEQ / 128), thr>>>(kvlat, wv_up, vbuf, SEQ, NH * DV, KVR);

    // rope on q_pe / k_pe
    rope_kernel<<<(SEQ * NH * 32) / 256, thr>>>(qbuf, kbuf);

    // causal attention
    attn_kernel<<<dim3(SEQ / BQ, NH), thr>>>(qbuf, kbuf, vbuf, attn);

    // output projection
    sgemm128<<<dim3(H_DIM / 128, SEQ / 128), thr>>>(attn, wo, out, SEQ, H_DIM, NH * DV);
}

// round 3
// speedup vs baseline: 1.1924x; 1.1924x over previous
#include <cuda_runtime.h>
#include <math.h>
#include <stdint.h>

#define H_DIM 2048
#define NH 16
#define DN 128
#define DR 64
#define DQ 192
#define DV 128
#define KVR 512
#define QR 1536
#define SEQ 2048
#define THETA 100000.0f
#define RMS_EPS 1e-5f

// ---------------- scratch ----------------
__device__ float g_qlat[SEQ * QR];
__device__ float g_q[SEQ * NH * DQ];
__device__ float g_kvlat[SEQ * KVR];
__device__ float g_k[SEQ * NH * DQ];
__device__ float g_v[SEQ * NH * DV];
__device__ float g_attn[SEQ * NH * DV];

// ---------------- tf32 helpers ----------------
__device__ __forceinline__ uint32_t f2tf32(float v) {
    uint32_t u;
    asm("cvt.rna.tf32.f32 %0, %1;" : "=r"(u) : "f"(v));
    return u;
}

__device__ __forceinline__ void mma_tf32(
    float& c0, float& c1, float& c2, float& c3,
    uint32_t a0, uint32_t a1, uint32_t a2, uint32_t a3,
    uint32_t b0, uint32_t b1)
{
    asm volatile(
        "mma.sync.aligned.m16n8k8.row.col.f32.tf32.tf32.f32 "
        "{%0,%1,%2,%3}, {%4,%5,%6,%7}, {%8,%9}, {%0,%1,%2,%3};"
        : "+f"(c0), "+f"(c1), "+f"(c2), "+f"(c3)
        : "r"(a0), "r"(a1), "r"(a2), "r"(a3), "r"(b0), "r"(b1));
}

// swizzled smem index: tile is [32 k][128 mn], word index
__device__ __forceinline__ int sw(int k, int mn) {
    return k * 128 + (mn ^ ((k & 3) << 3) ^ (((k >> 2) & 7) << 2));
}

// ---------------- tf32 tensor-core GEMM ----------------
// C[M,N] = A[M,K] @ B[K,N], row-major. M%128==0, N%128==0, K%32==0.
// 256 threads, warp grid 2(m) x 4(n), warp tile 64x32.
__global__ __launch_bounds__(256, 2) void sgemm_tf32(
    const float* __restrict__ A, const float* __restrict__ B,
    float* __restrict__ C, int M, int N, int K)
{
    __shared__ uint32_t As[32 * 128];
    __shared__ uint32_t Bs[32 * 128];

    const int bx = blockIdx.x, by = blockIdx.y;
    const int tid = threadIdx.x;
    const int wid = tid >> 5, lane = tid & 31;
    const int g = lane >> 2, tig = lane & 3;
    const int wm = wid & 1, wn = wid >> 1;

    const float* Ab = A + (size_t)by * 128 * K;
    const float* Bb = B + (size_t)bx * 128;

    float acc[4][4][4];
#pragma unroll
    for (int i = 0; i < 4; i++)
#pragma unroll
        for (int j = 0; j < 4; j++)
#pragma unroll
            for (int r = 0; r < 4; r++) acc[i][j][r] = 0.f;

    for (int k0 = 0; k0 < K; k0 += 32) {
        // load A tile: 128m x 32k = 1024 float4, 4 per thread
#pragma unroll
        for (int l = 0; l < 4; l++) {
            int f = tid + l * 256;
            int m = f >> 3;
            int k4 = (f & 7) * 4;
            float4 av = *reinterpret_cast<const float4*>(Ab + (size_t)m * K + k0 + k4);
            As[sw(k4 + 0, m)] = f2tf32(av.x);
            As[sw(k4 + 1, m)] = f2tf32(av.y);
            As[sw(k4 + 2, m)] = f2tf32(av.z);
            As[sw(k4 + 3, m)] = f2tf32(av.w);
        }
        // load B tile: 32k x 128n = 1024 float4, 4 per thread (float4 stores)
#pragma unroll
        for (int l = 0; l < 4; l++) {
            int f = tid + l * 256;
            int k = f >> 5;
            int n4 = (f & 31) * 4;
            float4 bv = *reinterpret_cast<const float4*>(Bb + (size_t)(k0 + k) * N + n4);
            int s = ((k & 3) << 3) ^ (((k >> 2) & 7) << 2);
            uint4 tv = make_uint4(f2tf32(bv.x), f2tf32(bv.y), f2tf32(bv.z), f2tf32(bv.w));
            *reinterpret_cast<uint4*>(&Bs[k * 128 + (n4 ^ s)]) = tv;
        }
        __syncthreads();

#pragma unroll
        for (int kk = 0; kk < 32; kk += 8) {
            const int ka = kk + tig, ka4 = ka + 4;
            uint32_t a[4][4], b[4][2];
#pragma unroll
            for (int i = 0; i < 4; i++) {
                int m0 = wm * 64 + i * 16 + g;
                a[i][0] = As[sw(ka, m0)];
                a[i][1] = As[sw(ka, m0 + 8)];
                a[i][2] = As[sw(ka4, m0)];
                a[i][3] = As[sw(ka4, m0 + 8)];
            }
#pragma unroll
            for (int j = 0; j < 4; j++) {
                int n0 = wn * 32 + j * 8 + g;
                b[j][0] = Bs[sw(ka, n0)];
                b[j][1] = Bs[sw(ka4, n0)];
            }
#pragma unroll
            for (int i = 0; i < 4; i++)
#pragma unroll
                for (int j = 0; j < 4; j++)
                    mma_tf32(acc[i][j][0], acc[i][j][1], acc[i][j][2], acc[i][j][3],
                             a[i][0], a[i][1], a[i][2], a[i][3], b[j][0], b[j][1]);
        }
        __syncthreads();
    }

    // epilogue: c0,c1 at (row g, cols 2*tig, 2*tig+1); c2,c3 at row g+8
    float* Cb = C + (size_t)(by * 128) * N + bx * 128;
#pragma unroll
    for (int i = 0; i < 4; i++) {
        int r0 = wm * 64 + i * 16 + g;
#pragma unroll
        for (int j = 0; j < 4; j++) {
            int cb = wn * 32 + j * 8 + tig * 2;
            *reinterpret_cast<float2*>(Cb + (size_t)r0 * N + cb) =
                make_float2(acc[i][j][0], acc[i][j][1]);
            *reinterpret_cast<float2*>(Cb + (size_t)(r0 + 8) * N + cb) =
                make_float2(acc[i][j][2], acc[i][j][3]);
        }
    }
}

// ---------------- RMSNorm ----------------
__global__ __launch_bounds__(256) void rmsnorm_kernel(float* x, const float* __restrict__ w, int D)
{
    __shared__ float red[8];
    const int row = blockIdx.x;
    float* xr = x + (size_t)row * D;

    float ss = 0.f;
    for (int i = threadIdx.x; i < D; i += 256) {
        float v = xr[i];
        ss += v * v;
    }
#pragma unroll
    for (int o = 16; o > 0; o >>= 1) ss += __shfl_xor_sync(0xffffffffu, ss, o);
    int wid = threadIdx.x >> 5, lid = threadIdx.x & 31;
    if (lid == 0) red[wid] = ss;
    __syncthreads();
    if (wid == 0) {
        ss = (lid < 8) ? red[lid] : 0.f;
#pragma unroll
        for (int o = 4; o > 0; o >>= 1) ss += __shfl_xor_sync(0xffffffffu, ss, o);
        if (lid == 0) red[0] = ss;
    }
    __syncthreads();
    float inv = rsqrtf(red[0] / (float)D + RMS_EPS);
    for (int i = threadIdx.x; i < D; i += 256) xr[i] = w[i] * xr[i] * inv;
}

// ---------------- RoPE ----------------
__global__ __launch_bounds__(256) void rope_kernel(float* q, float* k)
{
    int idx = blockIdx.x * blockDim.x + threadIdx.x;
    if (idx >= SEQ * NH * 32) return;
    int j = idx & 31;
    int h = (idx >> 5) & (NH - 1);
    int s = idx >> 9;

    float invf = powf(THETA, -(float)j / 32.0f);
    float ang = (float)s * invf;
    float sn, cs;
    sincosf(ang, &sn, &cs);

    float* qp = q + ((size_t)s * NH + h) * DQ + DN;
    float x1 = qp[j], x2 = qp[j + 32];
    qp[j] = x1 * cs - x2 * sn;
    qp[j + 32] = x2 * cs + x1 * sn;

    float* kp = k + ((size_t)s * NH + h) * DQ + DN;
    x1 = kp[j]; x2 = kp[j + 32];
    kp[j] = x1 * cs - x2 * sn;
    kp[j + 32] = x2 * cs + x1 * sn;
}

// ---------------- Flash attention, fp32, causal ----------------
#define BQ 64
#define BK 32
__global__ __launch_bounds__(256) void attn_kernel(
    const float* __restrict__ q, const float* __restrict__ k,
    const float* __restrict__ v, float* __restrict__ o)
{
    __shared__ float Ks[BK][DQ];
    __shared__ float Vs[BK][DV];

    const int qb = blockIdx.x, h = blockIdx.y;
    const int tid = threadIdx.x;
    const int r = tid >> 2;
    const int c = tid & 3;
    const int qrow = qb * BQ + r;
    const float scale = rsqrtf((float)DQ);

    float qf[48];
    const float* qp = q + ((size_t)qrow * NH + h) * DQ + c * 48;
#pragma unroll
    for (int i = 0; i < 12; i++) {
        float4 t = *reinterpret_cast<const float4*>(qp + i * 4);
        qf[i * 4 + 0] = t.x; qf[i * 4 + 1] = t.y; qf[i * 4 + 2] = t.z; qf[i * 4 + 3] = t.w;
    }

    float m = -1e30f, l = 0.f;
    float acc[32];
#pragma unroll
    for (int j = 0; j < 32; j++) acc[j] = 0.f;

    const int ntiles = (qb * BQ + BQ) / BK;
    for (int t = 0; t < ntiles; t++) {
        const int k0 = t * BK;
#pragma unroll
        for (int li = 0; li < 6; li++) {
            int f = tid + li * 256;
            int row = f / 48;
            int col = f % 48;
            float4 t4 = *reinterpret_cast<const float4*>(
                k + ((size_t)(k0 + row) * NH + h) * DQ + col * 4);
            *reinterpret_cast<float4*>(&Ks[row][col * 4]) = t4;
        }
#pragma unroll
        for (int li = 0; li < 4; li++) {
            int f = tid + li * 256;
            int row = f >> 5;
            int col = f & 31;
            float4 t4 = *reinterpret_cast<const float4*>(
                v + ((size_t)(k0 + row) * NH + h) * DV + col * 4);
            *reinterpret_cast<float4*>(&Vs[row][col * 4]) = t4;
        }
        __syncthreads();

        float sc[BK];
#pragma unroll
        for (int kk = 0; kk < BK; kk++) {
            float p = 0.f;
            const float4* kr4 = reinterpret_cast<const float4*>(&Ks[kk][c * 48]);
#pragma unroll
            for (int d4 = 0; d4 < 12; d4++) {
                float4 t4 = kr4[d4];
                p = fmaf(qf[d4 * 4 + 0], t4.x, p);
                p = fmaf(qf[d4 * 4 + 1], t4.y, p);
                p = fmaf(qf[d4 * 4 + 2], t4.z, p);
                p = fmaf(qf[d4 * 4 + 3], t4.w, p);
            }
            p += __shfl_xor_sync(0xffffffffu, p, 1);
            p += __shfl_xor_sync(0xffffffffu, p, 2);
            p *= scale;
            if (k0 + kk > qrow) p = -1e30f;
            sc[kk] = p;
        }

        float mt = m;
#pragma unroll
        for (int kk = 0; kk < BK; kk++) mt = fmaxf(mt, sc[kk]);
        float corr = __expf(m - mt);
        m = mt;
        l *= corr;
#pragma unroll
        for (int j = 0; j < 32; j++) acc[j] *= corr;

#pragma unroll
        for (int kk = 0; kk < BK; kk++) {
            float p = __expf(sc[kk] - m);
            l += p;
            const float4* vr4 = reinterpret_cast<const float4*>(&Vs[kk][c * 32]);
#pragma unroll
            for (int j4 = 0; j4 < 8; j4++) {
                float4 t4 = vr4[j4];
                acc[j4 * 4 + 0] = fmaf(p, t4.x, acc[j4 * 4 + 0]);
                acc[j4 * 4 + 1] = fmaf(p, t4.y, acc[j4 * 4 + 1]);
                acc[j4 * 4 + 2] = fmaf(p, t4.z, acc[j4 * 4 + 2]);
                acc[j4 * 4 + 3] = fmaf(p, t4.w, acc[j4 * 4 + 3]);
            }
        }
        __syncthreads();
    }

    float invl = 1.0f / l;
    float* op = o + ((size_t)qrow * NH + h) * DV + c * 32;
#pragma unroll
    for (int j4 = 0; j4 < 8; j4++) {
        float4 t4 = make_float4(acc[j4 * 4 + 0] * invl, acc[j4 * 4 + 1] * invl,
                                acc[j4 * 4 + 2] * invl, acc[j4 * 4 + 3] * invl);
        *reinterpret_cast<float4*>(op + j4 * 4) = t4;
    }
}

// ---------------- host launcher ----------------
extern "C" void kernel_launch(void* const* d_in, const int* in_sizes, int n_in,
                              void* d_out, int out_size)
{
    const float* x        = (const float*)d_in[0];
    const float* wq_down  = (const float*)d_in[1];
    const float* q_norm_w = (const float*)d_in[2];
    const float* wq_up    = (const float*)d_in[3];
    const float* wkv_down = (const float*)d_in[4];
    const float* kv_norm_w= (const float*)d_in[5];
    const float* wk_up    = (const float*)d_in[6];
    const float* wv_up    = (const float*)d_in[7];
    const float* wo       = (const float*)d_in[8];
    float* out = (float*)d_out;

    float *qlat, *qbuf, *kvlat, *kbuf, *vbuf, *attn;
    cudaGetSymbolAddress((void**)&qlat,  g_qlat);
    cudaGetSymbolAddress((void**)&qbuf,  g_q);
    cudaGetSymbolAddress((void**)&kvlat, g_kvlat);
    cudaGetSymbolAddress((void**)&kbuf,  g_k);
    cudaGetSymbolAddress((void**)&vbuf,  g_v);
    cudaGetSymbolAddress((void**)&attn,  g_attn);

    dim3 thr(256);

    // q path
    sgemm_tf32<<<dim3(QR / 128, SEQ / 128), thr>>>(x, wq_down, qlat, SEQ, QR, H_DIM);
    rmsnorm_kernel<<<SEQ, thr>>>(qlat, q_norm_w, QR);
    sgemm_tf32<<<dim3((NH * DQ) / 128, SEQ / 128), thr>>>(qlat, wq_up, qbuf, SEQ, NH * DQ, QR);

    // kv path
    sgemm_tf32<<<dim3(KVR / 128, SEQ / 128), thr>>>(x, wkv_down, kvlat, SEQ, KVR, H_DIM);
    rmsnorm_kernel<<<SEQ, thr>>>(kvlat, kv_norm_w, KVR);
    sgemm_tf32<<<dim3((NH * DQ) / 128, SEQ / 128), thr>>>(kvlat, wk_up, kbuf, SEQ, NH * DQ, KVR);
    sgemm_tf32<<<dim3((NH * DV) / 128, SEQ / 128), thr>>>(kvlat, wv_up, vbuf, SEQ, NH * DV, KVR);

    // rope
    rope_kernel<<<(SEQ * NH * 32) / 256, thr>>>(qbuf, kbuf);

    // causal attention
    attn_kernel<<<dim3(SEQ / BQ, NH), thr>>>(qbuf, kbuf, vbuf, attn);

    // output projection
    sgemm_tf32<<<dim3(H_DIM / 128, SEQ / 128), thr>>>(attn, wo, out, SEQ, H_DIM, NH * DV);
}

// round 4
// speedup vs baseline: 5.8345x; 4.8931x over previous
#include <cuda_runtime.h>
#include <math.h>
#include <stdint.h>

#define H_DIM 2048
#define NH 16
#define DN 128
#define DR 64
#define DQ 192
#define DV 128
#define KVR 512
#define QR 1536
#define SEQ 2048
#define THETA 100000.0f
#define RMS_EPS 1e-5f

// ---------------- scratch ----------------
__device__ float g_qlat[SEQ * QR];
__device__ float g_q[SEQ * NH * DQ];
__device__ float g_kvlat[SEQ * KVR];
__device__ float g_k[SEQ * NH * DQ];
__device__ float g_v[SEQ * NH * DV];
__device__ float g_attn[SEQ * NH * DV];

// ---------------- helpers ----------------
__device__ __forceinline__ uint32_t f2tf32(float v) {
    uint32_t u;
    asm("cvt.rna.tf32.f32 %0, %1;" : "=r"(u) : "f"(v));
    return u;
}

__device__ __forceinline__ void mma_tf32(
    float& c0, float& c1, float& c2, float& c3,
    uint32_t a0, uint32_t a1, uint32_t a2, uint32_t a3,
    uint32_t b0, uint32_t b1)
{
    asm volatile(
        "mma.sync.aligned.m16n8k8.row.col.f32.tf32.tf32.f32 "
        "{%0,%1,%2,%3}, {%4,%5,%6,%7}, {%8,%9}, {%0,%1,%2,%3};"
        : "+f"(c0), "+f"(c1), "+f"(c2), "+f"(c3)
        : "r"(a0), "r"(a1), "r"(a2), "r"(a3), "r"(b0), "r"(b1));
}

// fast exp on FMA pipe (x <= 0 expected; handles -1e30 mask via clamp)
__device__ __forceinline__ float fexp(float x) {
    x = fmaxf(x, -80.f) * 1.4426950408889634f;
    float z = x + 12582912.f;                    // round(x) in mantissa
    int n = __float_as_int(z) - 0x4B400000;
    float f = x - (z - 12582912.f);              // [-0.5, 0.5]
    float p = 1.3333558146e-3f;
    p = fmaf(p, f, 9.6180209e-3f);
    p = fmaf(p, f, 5.5504109e-2f);
    p = fmaf(p, f, 2.4022651e-1f);
    p = fmaf(p, f, 6.9314718e-1f);
    p = fmaf(p, f, 1.0f);
    return p * __int_as_float((n + 127) << 23);
}

// ---------------- tf32 GEMM v2: double-buffered, padded strides ----------------
// C[M,N] = A[M,K] @ B[K,N] row-major. M%128==0, N%128==0, K%16==0.
// As[m][k]: stride 20 words; Bs[k][n]: stride 136 words. 256 threads, 8 warps 2x4.
#define AST 20
#define BST 136
#define ASZ (128 * AST)
#define BSZ (16 * BST)

__global__ __launch_bounds__(256) void sgemm_tf32_v2(
    const float* __restrict__ A, const float* __restrict__ B,
    float* __restrict__ C, int M, int N, int K)
{
    __shared__ uint32_t As[2 * ASZ];
    __shared__ uint32_t Bs[2 * BSZ];

    const int bx = blockIdx.x, by = blockIdx.y;
    const int tid = threadIdx.x;
    const int wid = tid >> 5, lane = tid & 31;
    const int g = lane >> 2, tig = lane & 3;
    const int wm = wid & 1, wn = wid >> 1;

    // global load assignment
    const int am = tid >> 2, ak4 = (tid & 3) * 4;        // A: 2 f4 (rows am, am+64)
    const int bk = tid >> 5, bn4 = (tid & 31) * 4;       // B: 2 f4 (rows bk, bk+8)
    const float* pA0 = A + (size_t)(by * 128 + am) * K + ak4;
    const float* pA1 = pA0 + (size_t)64 * K;
    const float* pB0 = B + (size_t)bk * N + bx * 128 + bn4;
    const float* pB1 = pB0 + (size_t)8 * N;

    // smem store word offsets
    const int sa0 = am * AST + ak4, sa1 = (am + 64) * AST + ak4;
    const int sb0 = bk * BST + bn4, sb1 = (bk + 8) * BST + bn4;

    // fragment base pointers
    const uint32_t* fA = As + (wm * 64 + g) * AST + tig;
    const uint32_t* fB = Bs + wn * 32 + g + tig * BST;

    float acc[4][4][4];
#pragma unroll
    for (int i = 0; i < 4; i++)
#pragma unroll
        for (int j = 0; j < 4; j++)
#pragma unroll
            for (int r = 0; r < 4; r++) acc[i][j][r] = 0.f;

    float4 ra0, ra1, rb0, rb1;

    // prologue: load + store stage 0
    ra0 = *reinterpret_cast<const float4*>(pA0);
    ra1 = *reinterpret_cast<const float4*>(pA1);
    rb0 = *reinterpret_cast<const float4*>(pB0);
    rb1 = *reinterpret_cast<const float4*>(pB1);
    {
        uint4 u;
        u = make_uint4(f2tf32(ra0.x), f2tf32(ra0.y), f2tf32(ra0.z), f2tf32(ra0.w));
        *reinterpret_cast<uint4*>(&As[sa0]) = u;
        u = make_uint4(f2tf32(ra1.x), f2tf32(ra1.y), f2tf32(ra1.z), f2tf32(ra1.w));
        *reinterpret_cast<uint4*>(&As[sa1]) = u;
        u = make_uint4(f2tf32(rb0.x), f2tf32(rb0.y), f2tf32(rb0.z), f2tf32(rb0.w));
        *reinterpret_cast<uint4*>(&Bs[sb0]) = u;
        u = make_uint4(f2tf32(rb1.x), f2tf32(rb1.y), f2tf32(rb1.z), f2tf32(rb1.w));
        *reinterpret_cast<uint4*>(&Bs[sb1]) = u;
    }
    __syncthreads();

    int st = 0;
    for (int k0 = 16; k0 <= K; k0 += 16) {
        // prefetch next tile (if any)
        if (k0 < K) {
            ra0 = *reinterpret_cast<const float4*>(pA0 + k0);
            ra1 = *reinterpret_cast<const float4*>(pA1 + k0);
            rb0 = *reinterpret_cast<const float4*>(pB0 + (size_t)k0 * N);
            rb1 = *reinterpret_cast<const float4*>(pB1 + (size_t)k0 * N);
        }
        // compute current stage
        const uint32_t* cA = fA + st * ASZ;
        const uint32_t* cB = fB + st * BSZ;
#pragma unroll
        for (int kk = 0; kk < 16; kk += 8) {
            uint32_t a[4][4], b[4][2];
#pragma unroll
            for (int i = 0; i < 4; i++) {
                a[i][0] = cA[i * (16 * AST) + kk];
                a[i][1] = cA[i * (16 * AST) + 8 * AST + kk];
                a[i][2] = cA[i * (16 * AST) + kk + 4];
                a[i][3] = cA[i * (16 * AST) + 8 * AST + kk + 4];
            }
#pragma unroll
            for (int j = 0; j < 4; j++) {
                b[j][0] = cB[kk * BST + j * 8];
                b[j][1] = cB[(kk + 4) * BST + j * 8];
            }
#pragma unroll
            for (int i = 0; i < 4; i++)
#pragma unroll
                for (int j = 0; j < 4; j++)
                    mma_tf32(acc[i][j][0], acc[i][j][1], acc[i][j][2], acc[i][j][3],
                             a[i][0], a[i][1], a[i][2], a[i][3], b[j][0], b[j][1]);
        }
        // store next stage
        if (k0 < K) {
            int ns = st ^ 1;
            uint4 u;
            u = make_uint4(f2tf32(ra0.x), f2tf32(ra0.y), f2tf32(ra0.z), f2tf32(ra0.w));
            *reinterpret_cast<uint4*>(&As[ns * ASZ + sa0]) = u;
            u = make_uint4(f2tf32(ra1.x), f2tf32(ra1.y), f2tf32(ra1.z), f2tf32(ra1.w));
            *reinterpret_cast<uint4*>(&As[ns * ASZ + sa1]) = u;
            u = make_uint4(f2tf32(rb0.x), f2tf32(rb0.y), f2tf32(rb0.z), f2tf32(rb0.w));
            *reinterpret_cast<uint4*>(&Bs[ns * BSZ + sb0]) = u;
            u = make_uint4(f2tf32(rb1.x), f2tf32(rb1.y), f2tf32(rb1.z), f2tf32(rb1.w));
            *reinterpret_cast<uint4*>(&Bs[ns * BSZ + sb1]) = u;
            __syncthreads();
            st = ns;
        }
    }

    float* Cb = C + (size_t)(by * 128) * N + bx * 128;
#pragma unroll
    for (int i = 0; i < 4; i++) {
        int r0 = wm * 64 + i * 16 + g;
#pragma unroll
        for (int j = 0; j < 4; j++) {
            int cb = wn * 32 + j * 8 + tig * 2;
            *reinterpret_cast<float2*>(Cb + (size_t)r0 * N + cb) =
                make_float2(acc[i][j][0], acc[i][j][1]);
            *reinterpret_cast<float2*>(Cb + (size_t)(r0 + 8) * N + cb) =
                make_float2(acc[i][j][2], acc[i][j][3]);
        }
    }
}

// ---------------- RMSNorm ----------------
__global__ __launch_bounds__(256) void rmsnorm_kernel(float* x, const float* __restrict__ w, int D)
{
    __shared__ float red[8];
    const int row = blockIdx.x;
    float* xr = x + (size_t)row * D;

    float ss = 0.f;
    for (int i = threadIdx.x; i < D; i += 256) {
        float v = xr[i];
        ss += v * v;
    }
#pragma unroll
    for (int o = 16; o > 0; o >>= 1) ss += __shfl_xor_sync(0xffffffffu, ss, o);
    int wid = threadIdx.x >> 5, lid = threadIdx.x & 31;
    if (lid == 0) red[wid] = ss;
    __syncthreads();
    if (wid == 0) {
        ss = (lid < 8) ? red[lid] : 0.f;
#pragma unroll
        for (int o = 4; o > 0; o >>= 1) ss += __shfl_xor_sync(0xffffffffu, ss, o);
        if (lid == 0) red[0] = ss;
    }
    __syncthreads();
    float inv = rsqrtf(red[0] / (float)D + RMS_EPS);
    for (int i = threadIdx.x; i < D; i += 256) xr[i] = w[i] * xr[i] * inv;
}

// ---------------- RoPE ----------------
__global__ __launch_bounds__(256) void rope_kernel(float* q, float* k)
{
    int idx = blockIdx.x * blockDim.x + threadIdx.x;
    if (idx >= SEQ * NH * 32) return;
    int j = idx & 31;
    int h = (idx >> 5) & (NH - 1);
    int s = idx >> 9;

    float invf = powf(THETA, -(float)j / 32.0f);
    float ang = (float)s * invf;
    float sn, cs;
    sincosf(ang, &sn, &cs);

    float* qp = q + ((size_t)s * NH + h) * DQ + DN;
    float x1 = qp[j], x2 = qp[j + 32];
    qp[j] = x1 * cs - x2 * sn;
    qp[j + 32] = x2 * cs + x1 * sn;

    float* kp = k + ((size_t)s * NH + h) * DQ + DN;
    x1 = kp[j]; x2 = kp[j + 32];
    kp[j] = x1 * cs - x2 * sn;
    kp[j + 32] = x2 * cs + x1 * sn;
}

// ---------------- tensor-core flash attention (tf32), causal ----------------
// BQ=128 rows/block, 8 warps x 16 rows. K-tile = 64. P split hi/lo for PV.
#define AQ 128
#define AK 64
#define QST 196          // padded stride for Q/K rows (192 dims)
#define VST 136          // padded stride for V rows (128 dims)
#define QS_W (AQ * QST)
#define KS_W (AK * QST)
#define VS_W (AK * VST)
#define ATTN_SMEM ((QS_W + KS_W + VS_W) * 4)

extern __shared__ uint32_t smem_u[];

__global__ __launch_bounds__(256) void attn_tf32(
    const float* __restrict__ q, const float* __restrict__ k,
    const float* __restrict__ v, float* __restrict__ o)
{
    uint32_t* Qs = smem_u;
    uint32_t* Ks = smem_u + QS_W;
    uint32_t* Vs = Ks + KS_W;

    const int qb = gridDim.x - 1 - blockIdx.x;   // big blocks first
    const int h = blockIdx.y;
    const int tid = threadIdx.x;
    const int w = tid >> 5, lane = tid & 31;
    const int g = lane >> 2, tig = lane & 3;
    const int q0 = qb * AQ;
    const float scale = rsqrtf((float)DQ);

    // load Q tile (scaled, tf32): 128 rows x 48 f4
#pragma unroll
    for (int l = 0; l < 24; l++) {
        int f = tid + l * 256;
        int row = f / 48, c4 = (f % 48) * 4;
        float4 t4 = *reinterpret_cast<const float4*>(
            q + ((size_t)(q0 + row) * NH + h) * DQ + c4);
        uint4 u = make_uint4(f2tf32(t4.x * scale), f2tf32(t4.y * scale),
                             f2tf32(t4.z * scale), f2tf32(t4.w * scale));
        *reinterpret_cast<uint4*>(&Qs[row * QST + c4]) = u;
    }

    float oacc[16][4];
#pragma unroll
    for (int n = 0; n < 16; n++)
#pragma unroll
        for (int r = 0; r < 4; r++) oacc[n][r] = 0.f;
    float m0 = -1e30f, m1 = -1e30f, l0 = 0.f, l1 = 0.f;

    const uint32_t* fQ = Qs + (w * 16 + g) * QST + tig;
    const uint32_t* fK = Ks + g * QST + tig;
    const uint32_t* fV = Vs + tig * VST + g;

    const int niter = (q0 + AQ) / AK;
    for (int it = 0; it < niter; it++) {
        const int k0g = it * AK;
        // load K tile: 64 x 48 f4
#pragma unroll
        for (int l = 0; l < 12; l++) {
            int f = tid + l * 256;
            int row = f / 48, c4 = (f % 48) * 4;
            float4 t4 = *reinterpret_cast<const float4*>(
                k + ((size_t)(k0g + row) * NH + h) * DQ + c4);
            uint4 u = make_uint4(f2tf32(t4.x), f2tf32(t4.y), f2tf32(t4.z), f2tf32(t4.w));
            *reinterpret_cast<uint4*>(&Ks[row * QST + c4]) = u;
        }
        // load V tile: 64 x 32 f4
#pragma unroll
        for (int l = 0; l < 8; l++) {
            int f = tid + l * 256;
            int row = f >> 5, c4 = (f & 31) * 4;
            float4 t4 = *reinterpret_cast<const float4*>(
                v + ((size_t)(k0g + row) * NH + h) * DV + c4);
            uint4 u = make_uint4(f2tf32(t4.x), f2tf32(t4.y), f2tf32(t4.z), f2tf32(t4.w));
            *reinterpret_cast<uint4*>(&Vs[row * VST + c4]) = u;
        }
        __syncthreads();

        // S = Q @ K^T  (warp rows w*16..w*16+15, cols 0..63)
        float s[8][4];
#pragma unroll
        for (int j = 0; j < 8; j++)
#pragma unroll
            for (int r = 0; r < 4; r++) s[j][r] = 0.f;

#pragma unroll
        for (int kt = 0; kt < 24; kt++) {
            uint32_t a0 = fQ[kt * 8];
            uint32_t a1 = fQ[8 * QST + kt * 8];
            uint32_t a2 = fQ[kt * 8 + 4];
            uint32_t a3 = fQ[8 * QST + kt * 8 + 4];
#pragma unroll
            for (int j = 0; j < 8; j++) {
                uint32_t b0 = fK[j * (8 * QST) + kt * 8];
                uint32_t b1 = fK[j * (8 * QST) + kt * 8 + 4];
                mma_tf32(s[j][0], s[j][1], s[j][2], s[j][3], a0, a1, a2, a3, b0, b1);
            }
        }

        // causal mask
        const int r0 = q0 + w * 16 + g, r1 = r0 + 8;
        if (k0g + AK - 1 > r0) {
#pragma unroll
            for (int j = 0; j < 8; j++) {
                int c0 = k0g + j * 8 + tig * 2, c1 = c0 + 1;
                if (c0 > r0) s[j][0] = -1e30f;
                if (c1 > r0) s[j][1] = -1e30f;
                if (c0 > r1) s[j][2] = -1e30f;
                if (c1 > r1) s[j][3] = -1e30f;
            }
        }

        // online softmax
        float nm0 = -1e30f, nm1 = -1e30f;
#pragma unroll
        for (int j = 0; j < 8; j++) {
            nm0 = fmaxf(nm0, fmaxf(s[j][0], s[j][1]));
            nm1 = fmaxf(nm1, fmaxf(s[j][2], s[j][3]));
        }
        nm0 = fmaxf(nm0, __shfl_xor_sync(0xffffffffu, nm0, 1));
        nm0 = fmaxf(nm0, __shfl_xor_sync(0xffffffffu, nm0, 2));
        nm1 = fmaxf(nm1, __shfl_xor_sync(0xffffffffu, nm1, 1));
        nm1 = fmaxf(nm1, __shfl_xor_sync(0xffffffffu, nm1, 2));
        float mn0 = fmaxf(m0, nm0), mn1 = fmaxf(m1, nm1);
        float corr0 = fexp(m0 - mn0), corr1 = fexp(m1 - mn1);
        m0 = mn0; m1 = mn1;

        float rs0 = 0.f, rs1 = 0.f;
#pragma unroll
        for (int j = 0; j < 8; j++) {
            s[j][0] = fexp(s[j][0] - m0);
            s[j][1] = fexp(s[j][1] - m0);
            s[j][2] = fexp(s[j][2] - m1);
            s[j][3] = fexp(s[j][3] - m1);
            rs0 += s[j][0] + s[j][1];
            rs1 += s[j][2] + s[j][3];
        }
        rs0 += __shfl_xor_sync(0xffffffffu, rs0, 1);
        rs0 += __shfl_xor_sync(0xffffffffu, rs0, 2);
        rs1 += __shfl_xor_sync(0xffffffffu, rs1, 1);
        rs1 += __shfl_xor_sync(0xffffffffu, rs1, 2);
        l0 = l0 * corr0 + rs0;
        l1 = l1 * corr1 + rs1;

#pragma unroll
        for (int n = 0; n < 16; n++) {
            oacc[n][0] *= corr0; oacc[n][1] *= corr0;
            oacc[n][2] *= corr1; oacc[n][3] *= corr1;
        }

        // O += P @ V  (P split hi/lo via shfl-built A-frags)
        const int src0 = (lane & 28) | (tig >> 1);
        const int src1 = src0 | 2;
        const bool bs = (tig & 1);
#pragma unroll
        for (int kt = 0; kt < 8; kt++) {
            float v00 = __shfl_sync(0xffffffffu, s[kt][0], src0);
            float v01 = __shfl_sync(0xffffffffu, s[kt][1], src0);
            float v10 = __shfl_sync(0xffffffffu, s[kt][2], src0);
            float v11 = __shfl_sync(0xffffffffu, s[kt][3], src0);
            float w00 = __shfl_sync(0xffffffffu, s[kt][0], src1);
            float w01 = __shfl_sync(0xffffffffu, s[kt][1], src1);
            float w10 = __shfl_sync(0xffffffffu, s[kt][2], src1);
            float w11 = __shfl_sync(0xffffffffu, s[kt][3], src1);
            float fa0 = bs ? v01 : v00;
            float fa1 = bs ? v11 : v10;
            float fa2 = bs ? w01 : w00;
            float fa3 = bs ? w11 : w10;
            uint32_t ah0 = f2tf32(fa0), ah1 = f2tf32(fa1);
            uint32_t ah2 = f2tf32(fa2), ah3 = f2tf32(fa3);
            uint32_t al0 = f2tf32(fa0 - __uint_as_float(ah0));
            uint32_t al1 = f2tf32(fa1 - __uint_as_float(ah1));
            uint32_t al2 = f2tf32(fa2 - __uint_as_float(ah2));
            uint32_t al3 = f2tf32(fa3 - __uint_as_float(ah3));
#pragma unroll
            for (int nt = 0; nt < 16; nt++) {
                uint32_t b0 = fV[kt * (8 * VST) + nt * 8];
                uint32_t b1 = fV[kt * (8 * VST) + 4 * VST + nt * 8];
                mma_tf32(oacc[nt][0], oacc[nt][1], oacc[nt][2], oacc[nt][3],
                         ah0, ah1, ah2, ah3, b0, b1);
                mma_tf32(oacc[nt][0], oacc[nt][1], oacc[nt][2], oacc[nt][3],
                         al0, al1, al2, al3, b0, b1);
            }
        }
        __syncthreads();
    }

    const float il0 = 1.0f / l0, il1 = 1.0f / l1;
    const int r0 = q0 + w * 16 + g, r1 = r0 + 8;
    float* o0 = o + ((size_t)r0 * NH + h) * DV + tig * 2;
    float* o1 = o + ((size_t)r1 * NH + h) * DV + tig * 2;
#pragma unroll
    for (int nt = 0; nt < 16; nt++) {
        *reinterpret_cast<float2*>(o0 + nt * 8) = make_float2(oacc[nt][0] * il0, oacc[nt][1] * il0);
        *reinterpret_cast<float2*>(o1 + nt * 8) = make_float2(oacc[nt][2] * il1, oacc[nt][3] * il1);
    }
}

// ---------------- host launcher ----------------
extern "C" void kernel_launch(void* const* d_in, const int* in_sizes, int n_in,
                              void* d_out, int out_size)
{
    const float* x        = (const float*)d_in[0];
    const float* wq_down  = (const float*)d_in[1];
    const float* q_norm_w = (const float*)d_in[2];
    const float* wq_up    = (const float*)d_in[3];
    const float* wkv_down = (const float*)d_in[4];
    const float* kv_norm_w= (const float*)d_in[5];
    const float* wk_up    = (const float*)d_in[6];
    const float* wv_up    = (const float*)d_in[7];
    const float* wo       = (const float*)d_in[8];
    float* out = (float*)d_out;

    float *qlat, *qbuf, *kvlat, *kbuf, *vbuf, *attn;
    cudaGetSymbolAddress((void**)&qlat,  g_qlat);
    cudaGetSymbolAddress((void**)&qbuf,  g_q);
    cudaGetSymbolAddress((void**)&kvlat, g_kvlat);
    cudaGetSymbolAddress((void**)&kbuf,  g_k);
    cudaGetSymbolAddress((void**)&vbuf,  g_v);
    cudaGetSymbolAddress((void**)&attn,  g_attn);

    cudaFuncSetAttribute(attn_tf32, cudaFuncAttributeMaxDynamicSharedMemorySize, ATTN_SMEM);

    dim3 thr(256);

    // q path
    sgemm_tf32_v2<<<dim3(QR / 128, SEQ / 128), thr>>>(x, wq_down, qlat, SEQ, QR, H_DIM);
    rmsnorm_kernel<<<SEQ, thr>>>(qlat, q_norm_w, QR);
    sgemm_tf32_v2<<<dim3((NH * DQ) / 128, SEQ / 128), thr>>>(qlat, wq_up, qbuf, SEQ, NH * DQ, QR);

    // kv path
    sgemm_tf32_v2<<<dim3(KVR / 128, SEQ / 128), thr>>>(x, wkv_down, kvlat, SEQ, KVR, H_DIM);
    rmsnorm_kernel<<<SEQ, thr>>>(kvlat, kv_norm_w, KVR);
    sgemm_tf32_v2<<<dim3((NH * DQ) / 128, SEQ / 128), thr>>>(kvlat, wk_up, kbuf, SEQ, NH * DQ, KVR);
    sgemm_tf32_v2<<<dim3((NH * DV) / 128, SEQ / 128), thr>>>(kvlat, wv_up, vbuf, SEQ, NH * DV, KVR);

    // rope
    rope_kernel<<<(SEQ * NH * 32) / 256, thr>>>(qbuf, kbuf);

    // tensor-core causal attention
    attn_tf32<<<dim3(SEQ / AQ, NH), thr, ATTN_SMEM>>>(qbuf, kbuf, vbuf, attn);

    // output projection
    sgemm_tf32_v2<<<dim3(H_DIM / 128, SEQ / 128), thr>>>(attn, wo, out, SEQ, H_DIM, NH * DV);
}

// round 5
// speedup vs baseline: 6.5950x; 1.1304x over previous
#include <cuda_runtime.h>
#include <math.h>
#include <stdint.h>

#define H_DIM 2048
#define NH 16
#define DN 128
#define DR 64
#define DQ 192
#define DV 128
#define KVR 512
#define QR 1536
#define SEQ 2048
#define THETA 100000.0f
#define RMS_EPS 1e-5f

// ---------------- scratch ----------------
__device__ float g_qlat[SEQ * QR];
__device__ float g_q[SEQ * NH * DQ];
__device__ float g_kvlat[SEQ * KVR];
__device__ float g_k[SEQ * NH * DQ];
__device__ float g_v[SEQ * NH * DV];
__device__ float g_attn[SEQ * NH * DV];

// ---------------- helpers ----------------
__device__ __forceinline__ uint32_t f2tf32(float v) {
    uint32_t u;
    asm("cvt.rna.tf32.f32 %0, %1;" : "=r"(u) : "f"(v));
    return u;
}

__device__ __forceinline__ void mma_tf32(
    float& c0, float& c1, float& c2, float& c3,
    uint32_t a0, uint32_t a1, uint32_t a2, uint32_t a3,
    uint32_t b0, uint32_t b1)
{
    asm volatile(
        "mma.sync.aligned.m16n8k8.row.col.f32.tf32.tf32.f32 "
        "{%0,%1,%2,%3}, {%4,%5,%6,%7}, {%8,%9}, {%0,%1,%2,%3};"
        : "+f"(c0), "+f"(c1), "+f"(c2), "+f"(c3)
        : "r"(a0), "r"(a1), "r"(a2), "r"(a3), "r"(b0), "r"(b1));
}

__device__ __forceinline__ void cpa16(uint32_t saddr, const void* g) {
    asm volatile("cp.async.cg.shared.global [%0], [%1], 16;" :: "r"(saddr), "l"(g));
}
#define CP_COMMIT() asm volatile("cp.async.commit_group;")
#define CP_WAIT1()  asm volatile("cp.async.wait_group 1;")

// fast exp on FMA pipe
__device__ __forceinline__ float fexp(float x) {
    x = fmaxf(x, -80.f) * 1.4426950408889634f;
    float z = x + 12582912.f;
    int n = __float_as_int(z) - 0x4B400000;
    float f = x - (z - 12582912.f);
    float p = 1.3333558146e-3f;
    p = fmaf(p, f, 9.6180209e-3f);
    p = fmaf(p, f, 5.5504109e-2f);
    p = fmaf(p, f, 2.4022651e-1f);
    p = fmaf(p, f, 6.9314718e-1f);
    p = fmaf(p, f, 1.0f);
    return p * __int_as_float((n + 127) << 23);
}

// ---------------- tf32 GEMM v3: cp.async 3-stage pipeline, dual output ----------------
// Computes C1[M,N1] = A@B1 for bx < N1/128, else C2[M,N2] = A@B2.
// fp32 staged in smem, cvt.rna.tf32 at fragment load (same numerics as v2).
#define AST 20
#define BST 136
#define ASZ (128 * AST)
#define BSZ (16 * BST)
#define STAGES 3
#define GEMM_SMEM ((STAGES * (ASZ + BSZ)) * 4)

extern __shared__ float dsm[];

__global__ __launch_bounds__(256) void sgemm_tf32_v3(
    const float* __restrict__ A,
    const float* __restrict__ B1, float* __restrict__ C1, int nb1, int N1,
    const float* __restrict__ B2, float* __restrict__ C2, int N2,
    int K)
{
    float* Asf = dsm;
    float* Bsf = dsm + STAGES * ASZ;
    const uint32_t sbA = (uint32_t)__cvta_generic_to_shared(Asf);
    const uint32_t sbB = (uint32_t)__cvta_generic_to_shared(Bsf);

    int bx = blockIdx.x;
    const int by = blockIdx.y;
    const float* B;
    float* C;
    int N;
    if (bx < nb1) { B = B1; C = C1; N = N1; }
    else          { B = B2; C = C2; N = N2; bx -= nb1; }

    const int tid = threadIdx.x;
    const int wid = tid >> 5, lane = tid & 31;
    const int g = lane >> 2, tig = lane & 3;
    const int wm = wid & 1, wn = wid >> 1;

    const int am = tid >> 2, ak4 = (tid & 3) * 4;
    const int bk = tid >> 5, bn4 = (tid & 31) * 4;
    const float* pA0 = A + (size_t)(by * 128 + am) * K + ak4;
    const float* pA1 = pA0 + (size_t)64 * K;
    const float* pB0 = B + (size_t)bk * N + bx * 128 + bn4;
    const float* pB1 = pB0 + (size_t)8 * N;

    const uint32_t saA0 = sbA + (am * AST + ak4) * 4;
    const uint32_t saA1 = sbA + ((am + 64) * AST + ak4) * 4;
    const uint32_t saB0 = sbB + (bk * BST + bn4) * 4;
    const uint32_t saB1 = sbB + ((bk + 8) * BST + bn4) * 4;

    const float* fA = Asf + (wm * 64 + g) * AST + tig;
    const float* fB = Bsf + wn * 32 + g + tig * BST;

    float acc[4][4][4];
#pragma unroll
    for (int i = 0; i < 4; i++)
#pragma unroll
        for (int j = 0; j < 4; j++)
#pragma unroll
            for (int r = 0; r < 4; r++) acc[i][j][r] = 0.f;

    const int nt = K >> 4;

    // prologue: fill stages 0,1
#pragma unroll
    for (int s = 0; s < STAGES - 1; s++) {
        int k0 = s * 16;
        cpa16(saA0 + s * ASZ * 4, pA0 + k0);
        cpa16(saA1 + s * ASZ * 4, pA1 + k0);
        cpa16(saB0 + s * BSZ * 4, pB0 + (size_t)k0 * N);
        cpa16(saB1 + s * BSZ * 4, pB1 + (size_t)k0 * N);
        CP_COMMIT();
    }

    for (int it = 0; it < nt; it++) {
        CP_WAIT1();
        __syncthreads();

        // issue tile it+2 into slot (it+2)%3  (slot was consumed at it-1)
        if (it + STAGES - 1 < nt) {
            int s = (it + STAGES - 1) % STAGES;
            int k0 = (it + STAGES - 1) * 16;
            cpa16(saA0 + s * ASZ * 4, pA0 + k0);
            cpa16(saA1 + s * ASZ * 4, pA1 + k0);
            cpa16(saB0 + s * BSZ * 4, pB0 + (size_t)k0 * N);
            cpa16(saB1 + s * BSZ * 4, pB1 + (size_t)k0 * N);
        }
        CP_COMMIT();

        const float* cA = fA + (it % STAGES) * ASZ;
        const float* cB = fB + (it % STAGES) * BSZ;
#pragma unroll
        for (int kk = 0; kk < 16; kk += 8) {
            uint32_t a[4][4], b[4][2];
#pragma unroll
            for (int i = 0; i < 4; i++) {
                a[i][0] = f2tf32(cA[i * (16 * AST) + kk]);
                a[i][1] = f2tf32(cA[i * (16 * AST) + 8 * AST + kk]);
                a[i][2] = f2tf32(cA[i * (16 * AST) + kk + 4]);
                a[i][3] = f2tf32(cA[i * (16 * AST) + 8 * AST + kk + 4]);
            }
#pragma unroll
            for (int j = 0; j < 4; j++) {
                b[j][0] = f2tf32(cB[kk * BST + j * 8]);
                b[j][1] = f2tf32(cB[(kk + 4) * BST + j * 8]);
            }
#pragma unroll
            for (int i = 0; i < 4; i++)
#pragma unroll
                for (int j = 0; j < 4; j++)
                    mma_tf32(acc[i][j][0], acc[i][j][1], acc[i][j][2], acc[i][j][3],
                             a[i][0], a[i][1], a[i][2], a[i][3], b[j][0], b[j][1]);
        }
    }

    float* Cb = C + (size_t)(by * 128) * N + bx * 128;
#pragma unroll
    for (int i = 0; i < 4; i++) {
        int r0 = wm * 64 + i * 16 + g;
#pragma unroll
        for (int j = 0; j < 4; j++) {
            int cb = wn * 32 + j * 8 + tig * 2;
            *reinterpret_cast<float2*>(Cb + (size_t)r0 * N + cb) =
                make_float2(acc[i][j][0], acc[i][j][1]);
            *reinterpret_cast<float2*>(Cb + (size_t)(r0 + 8) * N + cb) =
                make_float2(acc[i][j][2], acc[i][j][3]);
        }
    }
}

// ---------------- RMSNorm ----------------
__global__ __launch_bounds__(256) void rmsnorm_kernel(float* x, const float* __restrict__ w, int D)
{
    __shared__ float red[8];
    const int row = blockIdx.x;
    float* xr = x + (size_t)row * D;

    float ss = 0.f;
    for (int i = threadIdx.x; i < D; i += 256) {
        float v = xr[i];
        ss += v * v;
    }
#pragma unroll
    for (int o = 16; o > 0; o >>= 1) ss += __shfl_xor_sync(0xffffffffu, ss, o);
    int wid = threadIdx.x >> 5, lid = threadIdx.x & 31;
    if (lid == 0) red[wid] = ss;
    __syncthreads();
    if (wid == 0) {
        ss = (lid < 8) ? red[lid] : 0.f;
#pragma unroll
        for (int o = 4; o > 0; o >>= 1) ss += __shfl_xor_sync(0xffffffffu, ss, o);
        if (lid == 0) red[0] = ss;
    }
    __syncthreads();
    float inv = rsqrtf(red[0] / (float)D + RMS_EPS);
    for (int i = threadIdx.x; i < D; i += 256) xr[i] = w[i] * xr[i] * inv;
}

// ---------------- RoPE ----------------
__global__ __launch_bounds__(256) void rope_kernel(float* q, float* k)
{
    int idx = blockIdx.x * blockDim.x + threadIdx.x;
    if (idx >= SEQ * NH * 32) return;
    int j = idx & 31;
    int h = (idx >> 5) & (NH - 1);
    int s = idx >> 9;

    float invf = powf(THETA, -(float)j / 32.0f);
    float ang = (float)s * invf;
    float sn, cs;
    sincosf(ang, &sn, &cs);

    float* qp = q + ((size_t)s * NH + h) * DQ + DN;
    float x1 = qp[j], x2 = qp[j + 32];
    qp[j] = x1 * cs - x2 * sn;
    qp[j + 32] = x2 * cs + x1 * sn;

    float* kp = k + ((size_t)s * NH + h) * DQ + DN;
    x1 = kp[j]; x2 = kp[j + 32];
    kp[j] = x1 * cs - x2 * sn;
    kp[j + 32] = x2 * cs + x1 * sn;
}

// ---------------- tensor-core flash attention (tf32), causal ----------------
#define AQ 128
#define AK 64
#define QST 196
#define VST 136
#define QS_W (AQ * QST)
#define KS_W (AK * QST)
#define VS_W (AK * VST)
#define ATTN_SMEM ((QS_W + KS_W + VS_W) * 4)

__global__ __launch_bounds__(256) void attn_tf32(
    const float* __restrict__ q, const float* __restrict__ k,
    const float* __restrict__ v, float* __restrict__ o)
{
    uint32_t* smem_u = reinterpret_cast<uint32_t*>(dsm);
    uint32_t* Qs = smem_u;
    uint32_t* Ks = smem_u + QS_W;
    uint32_t* Vs = Ks + KS_W;

    const int qb = gridDim.x - 1 - blockIdx.x;
    const int h = blockIdx.y;
    const int tid = threadIdx.x;
    const int w = tid >> 5, lane = tid & 31;
    const int g = lane >> 2, tig = lane & 3;
    const int q0 = qb * AQ;
    const float scale = rsqrtf((float)DQ);

#pragma unroll
    for (int l = 0; l < 24; l++) {
        int f = tid + l * 256;
        int row = f / 48, c4 = (f % 48) * 4;
        float4 t4 = *reinterpret_cast<const float4*>(
            q + ((size_t)(q0 + row) * NH + h) * DQ + c4);
        uint4 u = make_uint4(f2tf32(t4.x * scale), f2tf32(t4.y * scale),
                             f2tf32(t4.z * scale), f2tf32(t4.w * scale));
        *reinterpret_cast<uint4*>(&Qs[row * QST + c4]) = u;
    }

    float oacc[16][4];
#pragma unroll
    for (int n = 0; n < 16; n++)
#pragma unroll
        for (int r = 0; r < 4; r++) oacc[n][r] = 0.f;
    float m0 = -1e30f, m1 = -1e30f, l0 = 0.f, l1 = 0.f;

    const uint32_t* fQ = Qs + (w * 16 + g) * QST + tig;
    const uint32_t* fK = Ks + g * QST + tig;
    const uint32_t* fV = Vs + tig * VST + g;

    const int niter = (q0 + AQ) / AK;
    for (int it = 0; it < niter; it++) {
        const int k0g = it * AK;
#pragma unroll
        for (int l = 0; l < 12; l++) {
            int f = tid + l * 256;
            int row = f / 48, c4 = (f % 48) * 4;
            float4 t4 = *reinterpret_cast<const float4*>(
                k + ((size_t)(k0g + row) * NH + h) * DQ + c4);
            uint4 u = make_uint4(f2tf32(t4.x), f2tf32(t4.y), f2tf32(t4.z), f2tf32(t4.w));
            *reinterpret_cast<uint4*>(&Ks[row * QST + c4]) = u;
        }
#pragma unroll
        for (int l = 0; l < 8; l++) {
            int f = tid + l * 256;
            int row = f >> 5, c4 = (f & 31) * 4;
            float4 t4 = *reinterpret_cast<const float4*>(
                v + ((size_t)(k0g + row) * NH + h) * DV + c4);
            uint4 u = make_uint4(f2tf32(t4.x), f2tf32(t4.y), f2tf32(t4.z), f2tf32(t4.w));
            *reinterpret_cast<uint4*>(&Vs[row * VST + c4]) = u;
        }
        __syncthreads();

        float s[8][4];
#pragma unroll
        for (int j = 0; j < 8; j++)
#pragma unroll
            for (int r = 0; r < 4; r++) s[j][r] = 0.f;

#pragma unroll
        for (int kt = 0; kt < 24; kt++) {
            uint32_t a0 = fQ[kt * 8];
            uint32_t a1 = fQ[8 * QST + kt * 8];
            uint32_t a2 = fQ[kt * 8 + 4];
            uint32_t a3 = fQ[8 * QST + kt * 8 + 4];
#pragma unroll
            for (int j = 0; j < 8; j++) {
                uint32_t b0 = fK[j * (8 * QST) + kt * 8];
                uint32_t b1 = fK[j * (8 * QST) + kt * 8 + 4];
                mma_tf32(s[j][0], s[j][1], s[j][2], s[j][3], a0, a1, a2, a3, b0, b1);
            }
        }

        const int r0 = q0 + w * 16 + g, r1 = r0 + 8;
        if (k0g + AK - 1 > r0) {
#pragma unroll
            for (int j = 0; j < 8; j++) {
                int c0 = k0g + j * 8 + tig * 2, c1 = c0 + 1;
                if (c0 > r0) s[j][0] = -1e30f;
                if (c1 > r0) s[j][1] = -1e30f;
                if (c0 > r1) s[j][2] = -1e30f;
                if (c1 > r1) s[j][3] = -1e30f;
            }
        }

        float nm0 = -1e30f, nm1 = -1e30f;
#pragma unroll
        for (int j = 0; j < 8; j++) {
            nm0 = fmaxf(nm0, fmaxf(s[j][0], s[j][1]));
            nm1 = fmaxf(nm1, fmaxf(s[j][2], s[j][3]));
        }
        nm0 = fmaxf(nm0, __shfl_xor_sync(0xffffffffu, nm0, 1));
        nm0 = fmaxf(nm0, __shfl_xor_sync(0xffffffffu, nm0, 2));
        nm1 = fmaxf(nm1, __shfl_xor_sync(0xffffffffu, nm1, 1));
        nm1 = fmaxf(nm1, __shfl_xor_sync(0xffffffffu, nm1, 2));
        float mn0 = fmaxf(m0, nm0), mn1 = fmaxf(m1, nm1);
        float corr0 = fexp(m0 - mn0), corr1 = fexp(m1 - mn1);
        m0 = mn0; m1 = mn1;

        float rs0 = 0.f, rs1 = 0.f;
#pragma unroll
        for (int j = 0; j < 8; j++) {
            s[j][0] = fexp(s[j][0] - m0);
            s[j][1] = fexp(s[j][1] - m0);
            s[j][2] = fexp(s[j][2] - m1);
            s[j][3] = fexp(s[j][3] - m1);
            rs0 += s[j][0] + s[j][1];
            rs1 += s[j][2] + s[j][3];
        }
        rs0 += __shfl_xor_sync(0xffffffffu, rs0, 1);
        rs0 += __shfl_xor_sync(0xffffffffu, rs0, 2);
        rs1 += __shfl_xor_sync(0xffffffffu, rs1, 1);
        rs1 += __shfl_xor_sync(0xffffffffu, rs1, 2);
        l0 = l0 * corr0 + rs0;
        l1 = l1 * corr1 + rs1;

#pragma unroll
        for (int n = 0; n < 16; n++) {
            oacc[n][0] *= corr0; oacc[n][1] *= corr0;
            oacc[n][2] *= corr1; oacc[n][3] *= corr1;
        }

        const int src0 = (lane & 28) | (tig >> 1);
        const int src1 = src0 | 2;
        const bool bs = (tig & 1);
#pragma unroll
        for (int kt = 0; kt < 8; kt++) {
            float v00 = __shfl_sync(0xffffffffu, s[kt][0], src0);
            float v01 = __shfl_sync(0xffffffffu, s[kt][1], src0);
            float v10 = __shfl_sync(0xffffffffu, s[kt][2], src0);
            float v11 = __shfl_sync(0xffffffffu, s[kt][3], src0);
            float w00 = __shfl_sync(0xffffffffu, s[kt][0], src1);
            float w01 = __shfl_sync(0xffffffffu, s[kt][1], src1);
            float w10 = __shfl_sync(0xffffffffu, s[kt][2], src1);
            float w11 = __shfl_sync(0xffffffffu, s[kt][3], src1);
            float fa0 = bs ? v01 : v00;
            float fa1 = bs ? v11 : v10;
            float fa2 = bs ? w01 : w00;
            float fa3 = bs ? w11 : w10;
            uint32_t ah0 = f2tf32(fa0), ah1 = f2tf32(fa1);
            uint32_t ah2 = f2tf32(fa2), ah3 = f2tf32(fa3);
            uint32_t al0 = f2tf32(fa0 - __uint_as_float(ah0));
            uint32_t al1 = f2tf32(fa1 - __uint_as_float(ah1));
            uint32_t al2 = f2tf32(fa2 - __uint_as_float(ah2));
            uint32_t al3 = f2tf32(fa3 - __uint_as_float(ah3));
#pragma unroll
            for (int nt = 0; nt < 16; nt++) {
                uint32_t b0 = fV[kt * (8 * VST) + nt * 8];
                uint32_t b1 = fV[kt * (8 * VST) + 4 * VST + nt * 8];
                mma_tf32(oacc[nt][0], oacc[nt][1], oacc[nt][2], oacc[nt][3],
                         ah0, ah1, ah2, ah3, b0, b1);
                mma_tf32(oacc[nt][0], oacc[nt][1], oacc[nt][2], oacc[nt][3],
                         al0, al1, al2, al3, b0, b1);
            }
        }
        __syncthreads();
    }

    const float il0 = 1.0f / l0, il1 = 1.0f / l1;
    const int r0 = q0 + w * 16 + g, r1 = r0 + 8;
    float* o0 = o + ((size_t)r0 * NH + h) * DV + tig * 2;
    float* o1 = o + ((size_t)r1 * NH + h) * DV + tig * 2;
#pragma unroll
    for (int nt = 0; nt < 16; nt++) {
        *reinterpret_cast<float2*>(o0 + nt * 8) = make_float2(oacc[nt][0] * il0, oacc[nt][1] * il0);
        *reinterpret_cast<float2*>(o1 + nt * 8) = make_float2(oacc[nt][2] * il1, oacc[nt][3] * il1);
    }
}

// ---------------- host launcher ----------------
extern "C" void kernel_launch(void* const* d_in, const int* in_sizes, int n_in,
                              void* d_out, int out_size)
{
    const float* x        = (const float*)d_in[0];
    const float* wq_down  = (const float*)d_in[1];
    const float* q_norm_w = (const float*)d_in[2];
    const float* wq_up    = (const float*)d_in[3];
    const float* wkv_down = (const float*)d_in[4];
    const float* kv_norm_w= (const float*)d_in[5];
    const float* wk_up    = (const float*)d_in[6];
    const float* wv_up    = (const float*)d_in[7];
    const float* wo       = (const float*)d_in[8];
    float* out = (float*)d_out;

    float *qlat, *qbuf, *kvlat, *kbuf, *vbuf, *attn;
    cudaGetSymbolAddress((void**)&qlat,  g_qlat);
    cudaGetSymbolAddress((void**)&qbuf,  g_q);
    cudaGetSymbolAddress((void**)&kvlat, g_kvlat);
    cudaGetSymbolAddress((void**)&kbuf,  g_k);
    cudaGetSymbolAddress((void**)&vbuf,  g_v);
    cudaGetSymbolAddress((void**)&attn,  g_attn);

    static int inited = 0;
    cudaFuncSetAttribute(sgemm_tf32_v3, cudaFuncAttributeMaxDynamicSharedMemorySize, GEMM_SMEM);
    cudaFuncSetAttribute(attn_tf32, cudaFuncAttributeMaxDynamicSharedMemorySize, ATTN_SMEM);
    (void)inited;

    dim3 thr(256);

    // down projections (merged: share A = x)
    sgemm_tf32_v3<<<dim3((QR + KVR) / 128, SEQ / 128), thr, GEMM_SMEM>>>(
        x, wq_down, qlat, QR / 128, QR, wkv_down, kvlat, KVR, H_DIM);

    rmsnorm_kernel<<<SEQ, thr>>>(qlat, q_norm_w, QR);
    rmsnorm_kernel<<<SEQ, thr>>>(kvlat, kv_norm_w, KVR);

    // q up projection
    sgemm_tf32_v3<<<dim3((NH * DQ) / 128, SEQ / 128), thr, GEMM_SMEM>>>(
        qlat, wq_up, qbuf, (NH * DQ) / 128, NH * DQ, wq_up, qbuf, NH * DQ, QR);

    // k/v up projections (merged: share A = kvlat)
    sgemm_tf32_v3<<<dim3((NH * DQ + NH * DV) / 128, SEQ / 128), thr, GEMM_SMEM>>>(
        kvlat, wk_up, kbuf, (NH * DQ) / 128, NH * DQ, wv_up, vbuf, NH * DV, KVR);

    // rope
    rope_kernel<<<(SEQ * NH * 32) / 256, thr>>>(qbuf, kbuf);

    // tensor-core causal attention
    attn_tf32<<<dim3(SEQ / AQ, NH), thr, ATTN_SMEM>>>(qbuf, kbuf, vbuf, attn);

    // output projection
    sgemm_tf32_v3<<<dim3(H_DIM / 128, SEQ / 128), thr, GEMM_SMEM>>>(
        attn, wo, out, H_DIM / 128, H_DIM, wo, out, H_DIM, NH * DV);
}